// round 7
// baseline (speedup 1.0000x reference)
#include <cuda_runtime.h>
#include <cstdint>

// YOLO loss, fused single kernel: cp.async double-buffered streaming (R3
// skeleton) + warp-cooperative class softmax (all 32 lanes process one obj
// cell's 20 classes in parallel; ~3.2 obj cells per warp-tile).

#define TILE      128
#define THREADS   128
#define NPART_MAX 2048
#define NV4       ((TILE * 30) / 4)      // 960 float4 per array per tile

__device__ float        g_part[6][NPART_MAX];
__device__ unsigned int g_count = 0;

__device__ __forceinline__ void cp_async16(void* smem_dst, const void* gmem_src)
{
    uint32_t s = (uint32_t)__cvta_generic_to_shared(smem_dst);
    asm volatile("cp.async.cg.shared.global [%0], [%1], 16;" :: "r"(s), "l"(gmem_src));
}
__device__ __forceinline__ void cp_commit() { asm volatile("cp.async.commit_group;" ::: "memory"); }
__device__ __forceinline__ void cp_wait1()  { asm volatile("cp.async.wait_group 1;" ::: "memory"); }
__device__ __forceinline__ void cp_wait0()  { asm volatile("cp.async.wait_group 0;" ::: "memory"); }

struct Stage {
    float sp[TILE * 30];
    float st[TILE * 30];
    int   sc[TILE];
};

__device__ __forceinline__ void prefetch_tile(Stage* stg,
                                              const float* __restrict__ pred,
                                              const float* __restrict__ target,
                                              const int*   __restrict__ choice,
                                              long long base_cell, int tid)
{
    const float4* pg = (const float4*)(pred   + base_cell * 30);
    const float4* tg = (const float4*)(target + base_cell * 30);
    float4* sp4 = (float4*)stg->sp;
    float4* st4 = (float4*)stg->st;
    #pragma unroll
    for (int i = tid; i < NV4; i += THREADS) cp_async16(&sp4[i], &pg[i]);
    #pragma unroll
    for (int i = tid; i < NV4; i += THREADS) cp_async16(&st4[i], &tg[i]);
    if (tid < TILE / 4) {
        const float4* cg = (const float4*)(choice + base_cell);
        cp_async16(&((float4*)stg->sc)[tid], &cg[tid]);
    }
}

// cheap per-lane terms (loc/obj/noobj/counters); cls handled cooperatively
__device__ __forceinline__ bool lane_cheap(const float* __restrict__ p,
                                           const float* __restrict__ t,
                                           bool c, float acc[6])
{
    const float tconf = t[4];
    if (tconf > 0.f) {
        const int o = c ? 0 : 5;
        acc[4] += 1.f;
        float dx = p[o + 0] - t[o + 0];
        float dy = p[o + 1] - t[o + 1];
        float dw = p[o + 2] - sqrtf(t[o + 2]);
        float dh = p[o + 3] - sqrtf(t[o + 3]);
        acc[0] += 0.5f * (dx * dx + dy * dy) + 0.5f * (dw * dw + dh * dh);
        float tobj = c ? tconf : t[9];
        float d = p[o + 4] - tobj;
        acc[2] += d * d;
        return true;
    } else {
        acc[5] += 1.f;
        float d0 = p[4] - tconf;
        float d1 = p[9] - t[9];
        acc[3] += d0 * d0 + d1 * d1;
        return false;
    }
}

// warp-cooperative class CE for one cell; adds into lane 0's acc[1].
// ce = log(sum_j exp(sm_j)) - sm[argmax(tcls)], sm = softmax(logits).
__device__ __forceinline__ void coop_cls(const float* __restrict__ pc,
                                         const float* __restrict__ tc,
                                         int lane, float acc[6])
{
    const bool act = lane < 20;
    float x = act ? pc[10 + lane] : -1e30f;
    float m = x;
    #pragma unroll
    for (int o = 16; o > 0; o >>= 1) m = fmaxf(m, __shfl_xor_sync(0xffffffffu, m, o));
    float e = act ? __expf(x - m) : 0.f;
    float s = e;
    #pragma unroll
    for (int o = 16; o > 0; o >>= 1) s += __shfl_xor_sync(0xffffffffu, s, o);
    float smk = e * __fdividef(1.f, s);
    float e2 = act ? __expf(smk) : 0.f;
    float s2 = e2;
    #pragma unroll
    for (int o = 16; o > 0; o >>= 1) s2 += __shfl_xor_sync(0xffffffffu, s2, o);
    float lse2 = __logf(s2);

    float tv = act ? tc[10 + lane] : -1e30f;
    float bm = tv;
    #pragma unroll
    for (int o = 16; o > 0; o >>= 1) bm = fmaxf(bm, __shfl_xor_sync(0xffffffffu, bm, o));
    int cand = (act && tv == bm) ? lane : 32;   // first max -> lowest index
    #pragma unroll
    for (int o = 16; o > 0; o >>= 1) cand = min(cand, __shfl_xor_sync(0xffffffffu, cand, o));
    float smsel = __shfl_sync(0xffffffffu, smk, cand);

    if (lane == 0) acc[1] += lse2 - smsel;
}

__device__ __forceinline__ void block_reduce6(float* vals, float* s_red, int tid)
{
    #pragma unroll
    for (int v = 0; v < 6; v++) {
        #pragma unroll
        for (int off = 16; off > 0; off >>= 1)
            vals[v] += __shfl_down_sync(0xffffffffu, vals[v], off);
    }
    const int warp = tid >> 5;
    const int lane = tid & 31;
    if (lane == 0) {
        #pragma unroll
        for (int v = 0; v < 6; v++) s_red[warp * 6 + v] = vals[v];
    }
    __syncthreads();
    if (tid == 0) {
        #pragma unroll
        for (int v = 0; v < 6; v++)
            vals[v] = s_red[v] + s_red[6 + v] + s_red[12 + v] + s_red[18 + v];
    }
}

__global__ __launch_bounds__(THREADS)
void yolo_fused(const float* __restrict__ pred,
                const float* __restrict__ target,
                const int*   __restrict__ choice,
                float*       __restrict__ out,
                int n_cells, int n_tiles)
{
    __shared__ Stage stage[2];
    __shared__ float s_red[4 * 6];
    __shared__ bool  s_last;

    const int tid  = threadIdx.x;
    const int wid  = tid >> 5;
    const int lane = tid & 31;
    float acc[6] = {0.f, 0.f, 0.f, 0.f, 0.f, 0.f};

    const int first = blockIdx.x;
    const int step  = gridDim.x;

    int cur = 0;
    if (first < n_tiles) {
        long long base = (long long)first * TILE;
        if (base + TILE <= n_cells)
            prefetch_tile(&stage[0], pred, target, choice, base, tid);
        cp_commit();
    }

    for (int tile = first; tile < n_tiles; tile += step) {
        const long long base_cell = (long long)tile * TILE;
        const int cells_here = (int)min((long long)TILE, (long long)n_cells - base_cell);
        const bool full = (cells_here == TILE);

        const int next = tile + step;
        if (next < n_tiles) {
            long long nbase = (long long)next * TILE;
            if (nbase + TILE <= n_cells)
                prefetch_tile(&stage[cur ^ 1], pred, target, choice, nbase, tid);
            cp_commit();
            cp_wait1();
        } else {
            cp_wait0();
        }
        __syncthreads();   // stage ready; prior round's compute on this buffer done

        Stage* S = &stage[cur];

        if (full) {
            const float* p = S->sp + tid * 30;
            const float* t = S->st + tid * 30;
            bool ob = lane_cheap(p, t, S->sc[tid] != 0, acc);

            // cooperative class CE over this warp's obj cells, fixed bit order
            unsigned int mask = __ballot_sync(0xffffffffu, ob);
            const int warp_base = wid * 32;
            while (mask) {
                int b = __ffs(mask) - 1;
                mask &= mask - 1;
                int cell = warp_base + b;
                coop_cls(S->sp + cell * 30, S->st + cell * 30, lane, acc);
            }
        } else if (tid < cells_here) {
            // partial tail tile (never hit for 802816 cells): direct, serial CE
            const float* p = pred   + (base_cell + tid) * 30;
            const float* t = target + (base_cell + tid) * 30;
            if (lane_cheap(p, t, choice[base_cell + tid] != 0, acc)) {
                float mx = -1e30f;
                #pragma unroll
                for (int k = 0; k < 20; k++) mx = fmaxf(mx, p[10 + k]);
                float sm[20]; float den = 0.f;
                #pragma unroll
                for (int k = 0; k < 20; k++) { sm[k] = __expf(p[10 + k] - mx); den += sm[k]; }
                float inv = __fdividef(1.f, den);
                float den2 = 0.f;
                #pragma unroll
                for (int k = 0; k < 20; k++) { sm[k] *= inv; den2 += __expf(sm[k]); }
                float lse2 = __logf(den2);
                float bm = t[10]; int bi = 0;
                #pragma unroll
                for (int k = 1; k < 20; k++) { float v = t[10 + k]; if (v > bm) { bm = v; bi = k; } }
                acc[1] += lse2 - sm[bi];
            }
        }

        __syncthreads();   // all warps done reading stage[cur]
        cur ^= 1;
    }

    block_reduce6(acc, s_red, tid);

    if (tid == 0) {
        #pragma unroll
        for (int v = 0; v < 6; v++) g_part[v][blockIdx.x] = acc[v];
        __threadfence();
        unsigned int ticket = atomicAdd(&g_count, 1u);
        s_last = (ticket == gridDim.x - 1);
    }
    __syncthreads();

    if (s_last) {
        __threadfence();
        const int npart = gridDim.x;
        float a[6] = {0.f, 0.f, 0.f, 0.f, 0.f, 0.f};
        for (int i = tid; i < npart; i += THREADS) {
            #pragma unroll
            for (int v = 0; v < 6; v++) a[v] += g_part[v][i];
        }
        __syncthreads();
        block_reduce6(a, s_red, tid);
        if (tid == 0) {
            float n_obj = fmaxf(a[4], 1.f);
            float n_no  = fmaxf(a[5], 1.f);
            out[0] = 5.0f * a[0];
            out[1] = a[1] / n_obj;
            out[2] = a[2];
            out[3] = 0.5f * a[3] / n_no;
            g_count = 0;   // reset for next graph replay
        }
    }
}

extern "C" void kernel_launch(void* const* d_in, const int* in_sizes, int n_in,
                              void* d_out, int out_size)
{
    const float* pred   = (const float*)d_in[0];
    const float* target = (const float*)d_in[1];
    const int*   choice = (const int*)d_in[2];
    float* out = (float*)d_out;

    const int n_cells = in_sizes[2];
    const int n_tiles = (n_cells + TILE - 1) / TILE;

    int grid = 3 * 148;                       // 3 CTAs/SM, ~63 KB smem each
    if (grid > n_tiles) grid = n_tiles;
    if (grid > NPART_MAX) grid = NPART_MAX;

    yolo_fused<<<grid, THREADS>>>(pred, target, choice, out, n_cells, n_tiles);
}

// round 9
// speedup vs baseline: 1.1087x; 1.1087x over previous
#include <cuda_runtime.h>
#include <cstdint>

// YOLO loss: byte-reduced streaming. Only row "heads" (p[0..9], t[0..9], 40B
// each) are always fetched, via a sector-aware 16B-chunk pattern. Class blocks
// (80B x2) are fetched only for obj cells (~10%), deferred one round through a
// per-warp cp.async side buffer. Warps run independently (no block barriers).

#define THREADS   128
#define WARPS     4
#define MAXO      12           // obj slots per warp per stage (Binom(32,0.1): P(>12)~1e-6)
#define NPART_MAX 2048

__device__ float        g_part[6][NPART_MAX];
__device__ unsigned int g_count = 0;

__device__ __forceinline__ void cp_async16(void* s, const void* g)
{
    uint32_t sa = (uint32_t)__cvta_generic_to_shared(s);
    asm volatile("cp.async.cg.shared.global [%0], [%1], 16;" :: "r"(sa), "l"(g));
}
__device__ __forceinline__ void cp_async8(void* s, const void* g)
{
    uint32_t sa = (uint32_t)__cvta_generic_to_shared(s);
    asm volatile("cp.async.ca.shared.global [%0], [%1], 8;" :: "r"(sa), "l"(g));
}
__device__ __forceinline__ void cp_commit() { asm volatile("cp.async.commit_group;" ::: "memory"); }
template<int N> __device__ __forceinline__ void cp_wait()
{
    asm volatile("cp.async.wait_group %0;" :: "n"(N) : "memory");
}

// per-warp stage: head chunks (96 x 16B per array), choice, class side buffer
struct __align__(16) WStage {
    char  phead[1536];
    char  thead[1536];
    int   choice[32];
    float cls[MAXO][40];   // slot: pcls[20], tcls[20]
};                          // 5120 B

// ce = log(sum_j exp(sm_j)) - sm[argmax(tcls)], sm = softmax(logits); sm in
// [0,1] so the shiftless second LSE is safe. (validated rel_err ~1.6e-7)
__device__ __forceinline__ float serial_ce(const float* __restrict__ pc,
                                           const float* __restrict__ tc)
{
    float mx = -1e30f;
    #pragma unroll
    for (int k = 0; k < 20; k++) mx = fmaxf(mx, pc[k]);
    float sm[20]; float den = 0.f;
    #pragma unroll
    for (int k = 0; k < 20; k++) { sm[k] = __expf(pc[k] - mx); den += sm[k]; }
    float inv = __fdividef(1.f, den);
    float den2 = 0.f;
    #pragma unroll
    for (int k = 0; k < 20; k++) { sm[k] *= inv; den2 += __expf(sm[k]); }
    float lse2 = __logf(den2);
    float bm = tc[0]; int bi = 0;
    #pragma unroll
    for (int k = 1; k < 20; k++) { float v = tc[k]; if (v > bm) { bm = v; bi = k; } }
    return lse2 - sm[bi];
}

// cheap per-cell terms from head fields; returns obj flag
__device__ __forceinline__ bool cheap_terms(const float* __restrict__ ph,
                                            const float* __restrict__ th,
                                            bool c, float acc[6])
{
    float tconf = th[4];
    if (tconf > 0.f) {
        int o = c ? 0 : 5;
        acc[4] += 1.f;
        float dx = ph[o + 0] - th[o + 0];
        float dy = ph[o + 1] - th[o + 1];
        float dw = ph[o + 2] - sqrtf(th[o + 2]);
        float dh = ph[o + 3] - sqrtf(th[o + 3]);
        acc[0] += 0.5f * (dx * dx + dy * dy) + 0.5f * (dw * dw + dh * dh);
        float tobj = c ? tconf : th[9];
        float d = ph[o + 4] - tobj;
        acc[2] += d * d;
        return true;
    } else {
        acc[5] += 1.f;
        float d0 = ph[4] - tconf;
        float d1 = ph[9] - th[9];
        acc[3] += d0 * d0 + d1 * d1;
        return false;
    }
}

__device__ __forceinline__ void block_reduce6(float* vals, float* s_red, int tid)
{
    #pragma unroll
    for (int v = 0; v < 6; v++) {
        #pragma unroll
        for (int off = 16; off > 0; off >>= 1)
            vals[v] += __shfl_down_sync(0xffffffffu, vals[v], off);
    }
    const int warp = tid >> 5;
    const int lane = tid & 31;
    if (lane == 0) {
        #pragma unroll
        for (int v = 0; v < 6; v++) s_red[warp * 6 + v] = vals[v];
    }
    __syncthreads();
    if (tid == 0) {
        #pragma unroll
        for (int v = 0; v < 6; v++)
            vals[v] = s_red[v] + s_red[6 + v] + s_red[12 + v] + s_red[18 + v];
    }
}

__global__ __launch_bounds__(THREADS)
void yolo_fused(const float* __restrict__ pred,
                const float* __restrict__ target,
                const int*   __restrict__ choice,
                float*       __restrict__ out,
                int n_cells)
{
    __shared__ WStage ws[2][WARPS];
    __shared__ int    s_cnt[2][WARPS];
    __shared__ float  s_red[4 * 6];
    __shared__ bool   s_last;

    const int tid  = threadIdx.x;
    const int wid  = tid >> 5;
    const int lane = tid & 31;

    float acc[6] = {0.f, 0.f, 0.f, 0.f, 0.f, 0.f};

    const long long w  = (long long)blockIdx.x * WARPS + wid;   // global warp id
    const long long NW = (long long)gridDim.x * WARPS;
    const long long n_chunks = (long long)n_cells / 32;

    // per-lane head chunk mapping: chunk j in [0,96): global byte = (j/12)*480
    // + LUT[j%12] (16B chunks covering p/t[0..9] of 4 cells), smem byte = j*16
    const int LUT12[12] = {0,16,32,112,128,144,240,256,272,352,368,384};
    int gofs[3];
    #pragma unroll
    for (int k = 0; k < 3; k++) {
        int j = lane + 32 * k;
        int q = j / 12;
        gofs[k] = q * 480 + LUT12[j - q * 12];
    }

    auto issue_head = [&](int stg, long long ch) {
        WStage& S = ws[stg][wid];
        const char* gp = (const char*)pred   + ch * 3840;
        const char* gt = (const char*)target + ch * 3840;
        #pragma unroll
        for (int k = 0; k < 3; k++) {
            int j = lane + 32 * k;
            cp_async16(S.phead + j * 16, gp + gofs[k]);
            cp_async16(S.thead + j * 16, gt + gofs[k]);
        }
        if (lane < 8)
            cp_async16(&S.choice[lane * 4], (const char*)choice + ch * 128 + lane * 16);
    };

    // ---- prologue: heads for chunks w, w+NW as two groups ----
    if (w < n_chunks)      issue_head(0, w);
    cp_commit();
    if (w + NW < n_chunks) issue_head(1, w + NW);
    cp_commit();

    const int off4[4] = {0, 56, 96, 152};   // cell(r%4) head base within quad
    const int quad = lane >> 2, r4 = lane & 3;

    int stg = 0, round = 0;
    for (long long ch = w; ch < n_chunks; ch += NW, stg ^= 1, ++round) {
        // 1. head(ch) resident (prologue round needs wait 1, steady 2)
        if (round == 0) cp_wait<1>(); else cp_wait<2>();
        __syncwarp();

        WStage& S = ws[stg][wid];
        const float* ph = (const float*)(S.phead + quad * 192 + off4[r4]);
        const float* th = (const float*)(S.thead + quad * 192 + off4[r4]);
        const bool   c  = S.choice[lane] != 0;

        // 2. cheap terms + obj compaction
        bool ob = cheap_terms(ph, th, c, acc);
        unsigned mask = __ballot_sync(0xffffffffu, ob);
        if (lane == 0) s_cnt[stg][wid] = min(__popc(mask), MAXO);
        if (ob) {
            int slot = __popc(mask & ((1u << lane) - 1u));
            if (slot < MAXO) {
                // 3. issue class fetch for this cell into side buffer (8B, 8-aligned)
                const char* gpc = (const char*)pred   + ((ch * 32 + lane) * 120 + 40);
                const char* gtc = (const char*)target + ((ch * 32 + lane) * 120 + 40);
                float* dst = S.cls[slot];
                #pragma unroll
                for (int k = 0; k < 10; k++) cp_async8(dst + 2 * k, gpc + 8 * k);
                #pragma unroll
                for (int k = 0; k < 10; k++) cp_async8(dst + 20 + 2 * k, gtc + 8 * k);
            } else {
                // overflow (~never): synchronous direct CE
                const float* prow = pred   + (ch * 32 + lane) * 30;
                const float* trow = target + (ch * 32 + lane) * 30;
                acc[1] += serial_ce(prow + 10, trow + 10);
            }
        }
        cp_commit();                        // C group (uniform; empty for most lanes)

        // 4. deferred CE for previous chunk (its class data landed last round)
        if (round > 0) {
            cp_wait<2>();
            __syncwarp();
            int cnt = s_cnt[stg ^ 1][wid];
            if (lane < cnt) {
                const float* buf = ws[stg ^ 1][wid].cls[lane];
                acc[1] += serial_ce(buf, buf + 20);
            }
        }

        // 5. prefetch head for ch + 2*NW into this stage
        __syncwarp();                       // all lanes done reading this stage's head
        long long nch = ch + 2 * NW;
        if (nch < n_chunks) issue_head(stg, nch);
        cp_commit();                        // H group (always)
    }

    // epilogue: CE for the final chunk
    if (round > 0) {
        cp_wait<0>();
        __syncwarp();
        int pstg = (round - 1) & 1;
        int cnt = s_cnt[pstg][wid];
        if (lane < cnt) {
            const float* buf = ws[pstg][wid].cls[lane];
            acc[1] += serial_ce(buf, buf + 20);
        }
    }

    // tail cells (n_cells % 32; zero for this shape): direct
    if (blockIdx.x == 0 && wid == 0) {
        for (long long cell = n_chunks * 32 + lane; cell < n_cells; cell += 32) {
            const float* prow = pred   + cell * 30;
            const float* trow = target + cell * 30;
            if (cheap_terms(prow, trow, choice[cell] != 0, acc))
                acc[1] += serial_ce(prow + 10, trow + 10);
        }
    }

    __syncthreads();
    block_reduce6(acc, s_red, tid);

    if (tid == 0) {
        #pragma unroll
        for (int v = 0; v < 6; v++) g_part[v][blockIdx.x] = acc[v];
        __threadfence();
        unsigned int ticket = atomicAdd(&g_count, 1u);
        s_last = (ticket == gridDim.x - 1);
    }
    __syncthreads();

    if (s_last) {
        __threadfence();
        const int npart = gridDim.x;
        float a[6] = {0.f, 0.f, 0.f, 0.f, 0.f, 0.f};
        for (int i = tid; i < npart; i += THREADS) {
            #pragma unroll
            for (int v = 0; v < 6; v++) a[v] += g_part[v][i];
        }
        __syncthreads();
        block_reduce6(a, s_red, tid);
        if (tid == 0) {
            float n_obj = fmaxf(a[4], 1.f);
            float n_no  = fmaxf(a[5], 1.f);
            out[0] = 5.0f * a[0];
            out[1] = a[1] / n_obj;
            out[2] = a[2];
            out[3] = 0.5f * a[3] / n_no;
            g_count = 0;   // reset for next graph replay
        }
    }
}

extern "C" void kernel_launch(void* const* d_in, const int* in_sizes, int n_in,
                              void* d_out, int out_size)
{
    const float* pred   = (const float*)d_in[0];
    const float* target = (const float*)d_in[1];
    const int*   choice = (const int*)d_in[2];
    float* out = (float*)d_out;

    const int n_cells = in_sizes[2];

    int grid = 5 * 148;                      // 5 CTAs/SM @ ~41.5 KB smem
    if (grid > NPART_MAX) grid = NPART_MAX;
    if (grid < 1) grid = 1;

    yolo_fused<<<grid, THREADS>>>(pred, target, choice, out, n_cells);
}

// round 10
// speedup vs baseline: 1.2795x; 1.1541x over previous
#include <cuda_runtime.h>
#include <cstdint>

// YOLO loss "slim": no smem staging, no barriers in the main loop.
// Per cell always load 5 scalars (t4, choice, p4, p9, t9) -> deep MLP across
// 24 warps/SM. Full rows fetched only for obj cells (~10%), largely L1/L2 hits.

#define THREADS   256
#define NPART_MAX 2048

__device__ float        g_part[6][NPART_MAX];
__device__ unsigned int g_count = 0;

__device__ __forceinline__ void block_reduce6(float* vals, float* s_red, int tid)
{
    #pragma unroll
    for (int v = 0; v < 6; v++) {
        #pragma unroll
        for (int off = 16; off > 0; off >>= 1)
            vals[v] += __shfl_down_sync(0xffffffffu, vals[v], off);
    }
    const int warp = tid >> 5;
    const int lane = tid & 31;
    if (lane == 0) {
        #pragma unroll
        for (int v = 0; v < 6; v++) s_red[warp * 6 + v] = vals[v];
    }
    __syncthreads();
    if (tid == 0) {
        #pragma unroll
        for (int v = 0; v < 6; v++) {
            float s = 0.f;
            #pragma unroll
            for (int w2 = 0; w2 < THREADS / 32; w2++) s += s_red[w2 * 6 + v];
            vals[v] = s;
        }
    }
}

__global__ __launch_bounds__(THREADS, 3)
void yolo_slim(const float* __restrict__ pred,
               const float* __restrict__ target,
               const int*   __restrict__ choice,
               float*       __restrict__ out,
               int n_cells)
{
    __shared__ float s_red[(THREADS / 32) * 6];
    __shared__ bool  s_last;

    const int tid = threadIdx.x;
    float acc[6] = {0.f, 0.f, 0.f, 0.f, 0.f, 0.f};

    const long long stride = (long long)gridDim.x * THREADS;

    for (long long cell = (long long)blockIdx.x * THREADS + tid;
         cell < n_cells; cell += stride)
    {
        const float* p = pred   + cell * 30;
        const float* t = target + cell * 30;

        // always-needed scalars (5 independent loads -> MLP)
        const float t4 = t[4];
        const int   cv = choice[cell];
        const float p4 = p[4];
        const float p9 = p[9];
        const float t9 = t[9];

        if (t4 > 0.f) {
            // ---- obj cell (~10%): fetch rows (mostly cached lines) ----
            const bool c = cv != 0;
            const int  o = c ? 0 : 5;
            acc[4] += 1.f;

            float dx = p[o + 0] - t[o + 0];
            float dy = p[o + 1] - t[o + 1];
            float dw = p[o + 2] - sqrtf(t[o + 2]);
            float dh = p[o + 3] - sqrtf(t[o + 3]);
            acc[0] += 0.5f * (dx * dx + dy * dy) + 0.5f * (dw * dw + dh * dh);

            float pobj = c ? p4 : p9;
            float tobj = c ? t4 : t9;
            float d = pobj - tobj;
            acc[2] += d * d;

            // class logits: 10 aligned float2 loads (byte 40 within 120B row)
            float x[20];
            const float2* pc2 = (const float2*)(p + 10);
            #pragma unroll
            for (int k = 0; k < 10; k++) {
                float2 v = pc2[k];
                x[2 * k]     = v.x;
                x[2 * k + 1] = v.y;
            }
            float mx = -1e30f;
            #pragma unroll
            for (int k = 0; k < 20; k++) mx = fmaxf(mx, x[k]);
            float den = 0.f;
            #pragma unroll
            for (int k = 0; k < 20; k++) den += __expf(x[k] - mx);
            float inv = __fdividef(1.f, den);
            // den2 = sum exp(sm_k); sm in [0,1] -> shiftless LSE safe
            float den2 = 0.f;
            #pragma unroll
            for (int k = 0; k < 20; k++) den2 += __expf(__expf(x[k] - mx) * inv);
            float lse2 = __logf(den2);

            // argmax over target classes (first max), carrying matching logit
            const float2* tc2 = (const float2*)(t + 10);
            float bm = -1e30f, xsel = 0.f;
            #pragma unroll
            for (int k = 0; k < 10; k++) {
                float2 v = tc2[k];
                if (v.x > bm) { bm = v.x; xsel = x[2 * k]; }
                if (v.y > bm) { bm = v.y; xsel = x[2 * k + 1]; }
            }
            float smsel = __expf(xsel - mx) * inv;
            acc[1] += lse2 - smsel;
        } else {
            // ---- noobj cell: uses only already-loaded scalars ----
            acc[5] += 1.f;
            float d0 = p4 - t4;          // t4 == 0 here
            float d1 = p9 - t9;
            acc[3] += d0 * d0 + d1 * d1;
        }
    }

    __syncthreads();
    block_reduce6(acc, s_red, tid);

    if (tid == 0) {
        #pragma unroll
        for (int v = 0; v < 6; v++) g_part[v][blockIdx.x] = acc[v];
        __threadfence();
        unsigned int ticket = atomicAdd(&g_count, 1u);
        s_last = (ticket == gridDim.x - 1);
    }
    __syncthreads();

    if (s_last) {
        __threadfence();
        const int npart = gridDim.x;
        float a[6] = {0.f, 0.f, 0.f, 0.f, 0.f, 0.f};
        for (int i = tid; i < npart; i += THREADS) {
            #pragma unroll
            for (int v = 0; v < 6; v++) a[v] += g_part[v][i];
        }
        __syncthreads();
        block_reduce6(a, s_red, tid);
        if (tid == 0) {
            float n_obj = fmaxf(a[4], 1.f);
            float n_no  = fmaxf(a[5], 1.f);
            out[0] = 5.0f * a[0];          // loc_loss
            out[1] = a[1] / n_obj;         // cls_loss
            out[2] = a[2];                 // obj_loss
            out[3] = 0.5f * a[3] / n_no;   // noobj_loss
            g_count = 0;                   // reset for next graph replay
        }
    }
}

extern "C" void kernel_launch(void* const* d_in, const int* in_sizes, int n_in,
                              void* d_out, int out_size)
{
    const float* pred   = (const float*)d_in[0];
    const float* target = (const float*)d_in[1];
    const int*   choice = (const int*)d_in[2];
    float* out = (float*)d_out;

    const int n_cells = in_sizes[2];

    int grid = 3 * 148;                      // 3 CTAs/SM x 256 thr = 24 warps/SM
    long long want = ((long long)n_cells + THREADS - 1) / THREADS;
    if ((long long)grid > want) grid = (int)want;
    if (grid < 1) grid = 1;
    if (grid > NPART_MAX) grid = NPART_MAX;

    yolo_slim<<<grid, THREADS>>>(pred, target, choice, out, n_cells);
}